// round 1
// baseline (speedup 1.0000x reference)
#include <cuda_runtime.h>
#include <cuda_bf16.h>
#include <cstdint>

// Problem constants (from reference setup_inputs)
#define MAXN 50000
#define MAXE 800000
#define NGRAPH 512

// Scratch (device globals: allocation-free).
// g_P is reused by both layers: [N, 72] = [N][k=0..7 rows of 8][bias row of 8]
__device__ __align__(128) float g_P[(size_t)MAXN * 72];
__device__ __align__(128) float g_agg1[(size_t)MAXN * 8];
__device__ __align__(128) float g_agg2[(size_t)MAXN * 8];

// -----------------------------------------------------------------------------
// Node precompute: P[n,k,o] = sum_i in[n,i] * We[k, i*8+o]
//                  P[n,8,o] = sum_i in[n,i] * be[i*8+o]   (bias row)
//                  agg[n,o] = b[o] + sum_i in[n,i] * root[i,o]  (root init)
// One thread per (node, o). RELU applied to input when templated on.
// -----------------------------------------------------------------------------
template<int IN, bool RELU>
__global__ void node_prep_kernel(
    const float* __restrict__ xin,   // [N, IN] (pre-activation if RELU)
    const float* __restrict__ We,    // [8, IN*8]
    const float* __restrict__ be,    // [IN*8]
    const float* __restrict__ root,  // [IN, 8]
    const float* __restrict__ bvec,  // [8]
    float* __restrict__ P,           // [N, 72]
    float* __restrict__ agg,         // [N, 8]
    int N)
{
    __shared__ float sW[8 * IN * 8];
    __shared__ float sB[IN * 8];
    __shared__ float sR[IN * 8];
    __shared__ float sb[8];
    for (int i = threadIdx.x; i < 8 * IN * 8; i += blockDim.x) sW[i] = We[i];
    for (int i = threadIdx.x; i < IN * 8; i += blockDim.x) { sB[i] = be[i]; sR[i] = root[i]; }
    if (threadIdx.x < 8) sb[threadIdx.x] = bvec[threadIdx.x];
    __syncthreads();

    int idx = blockIdx.x * blockDim.x + threadIdx.x;
    int n = idx >> 3;
    int o = idx & 7;
    if (n >= N) return;

    float xv[IN];
#pragma unroll
    for (int i = 0; i < IN; i++) {
        float v = __ldg(xin + (size_t)n * IN + i);
        xv[i] = RELU ? fmaxf(v, 0.0f) : v;
    }

    float* Pr = P + (size_t)n * 72;
#pragma unroll
    for (int k = 0; k < 8; k++) {
        float acc = 0.0f;
#pragma unroll
        for (int i = 0; i < IN; i++) acc = fmaf(xv[i], sW[k * IN * 8 + i * 8 + o], acc);
        Pr[k * 8 + o] = acc;
    }
    float accb = 0.0f;
#pragma unroll
    for (int i = 0; i < IN; i++) accb = fmaf(xv[i], sB[i * 8 + o], accb);
    Pr[64 + o] = accb;

    float accr = sb[o];
#pragma unroll
    for (int i = 0; i < IN; i++) accr = fmaf(xv[i], sR[i * 8 + o], accr);
    agg[(size_t)n * 8 + o] = accr;
}

// -----------------------------------------------------------------------------
// Edge phase: msg[e,o] = P[src,8,o] + sum_k ea[e,k] * P[src,k,o]
// then scatter-add into agg[dst,:] with vector red.
// One thread per edge.
// -----------------------------------------------------------------------------
__global__ void edge_kernel(
    const int*   __restrict__ ei,   // [2, E] (src row, dst row)
    const float* __restrict__ ea,   // [E, 8]
    const float* __restrict__ P,    // [N, 72]
    float*       __restrict__ agg,  // [N, 8]
    int E)
{
    int e = blockIdx.x * blockDim.x + threadIdx.x;
    if (e >= E) return;

    int src = __ldg(ei + e);
    int dst = __ldg(ei + E + e);

    const float4* eap = reinterpret_cast<const float4*>(ea + (size_t)e * 8);
    float4 a0 = __ldg(eap);
    float4 a1 = __ldg(eap + 1);
    float c[8] = {a0.x, a0.y, a0.z, a0.w, a1.x, a1.y, a1.z, a1.w};

    const float4* p = reinterpret_cast<const float4*>(P + (size_t)src * 72);
    float4 m0 = __ldg(p + 16);  // bias row, o=0..3
    float4 m1 = __ldg(p + 17);  // bias row, o=4..7
#pragma unroll
    for (int k = 0; k < 8; k++) {
        float4 p0 = __ldg(p + 2 * k);
        float4 p1 = __ldg(p + 2 * k + 1);
        m0.x = fmaf(c[k], p0.x, m0.x);
        m0.y = fmaf(c[k], p0.y, m0.y);
        m0.z = fmaf(c[k], p0.z, m0.z);
        m0.w = fmaf(c[k], p0.w, m0.w);
        m1.x = fmaf(c[k], p1.x, m1.x);
        m1.y = fmaf(c[k], p1.y, m1.y);
        m1.z = fmaf(c[k], p1.z, m1.z);
        m1.w = fmaf(c[k], p1.w, m1.w);
    }

    float* outp = agg + (size_t)dst * 8;
    asm volatile("red.relaxed.gpu.global.add.v4.f32 [%0], {%1,%2,%3,%4};"
                 :: "l"(outp), "f"(m0.x), "f"(m0.y), "f"(m0.z), "f"(m0.w) : "memory");
    asm volatile("red.relaxed.gpu.global.add.v4.f32 [%0], {%1,%2,%3,%4};"
                 :: "l"(outp + 4), "f"(m1.x), "f"(m1.y), "f"(m1.z), "f"(m1.w) : "memory");
}

// -----------------------------------------------------------------------------
// Output init: out[g] = blast[0]
// -----------------------------------------------------------------------------
__global__ void init_out_kernel(float* __restrict__ out, const float* __restrict__ blast, int G)
{
    int i = blockIdx.x * blockDim.x + threadIdx.x;
    if (i < G) out[i] = __ldg(blast);
}

// -----------------------------------------------------------------------------
// Pool + readout: out[batch[n]] += relu(agg2[n]) . Wlast
// batch is sorted -> warp-segmented reduction before atomics.
// -----------------------------------------------------------------------------
__global__ void pool_kernel(
    const float* __restrict__ agg2,
    const int*   __restrict__ batch,
    const float* __restrict__ Wlast,  // [8]
    float*       __restrict__ out,    // [G]
    int N)
{
    int n = blockIdx.x * blockDim.x + threadIdx.x;
    int lane = threadIdx.x & 31;
    bool valid = (n < N);
    float s = 0.0f;
    int g = -1;
    if (valid) {
        g = __ldg(batch + n);
#pragma unroll
        for (int o = 0; o < 8; o++) {
            float h = fmaxf(__ldg(agg2 + (size_t)n * 8 + o), 0.0f);
            s = fmaf(h, __ldg(Wlast + o), s);
        }
    }
    // segmented suffix-sum over sorted keys within a warp
#pragma unroll
    for (int d = 1; d < 32; d <<= 1) {
        float v = __shfl_down_sync(0xffffffffu, s, d);
        int gg   = __shfl_down_sync(0xffffffffu, g, d);
        if (lane + d < 32 && gg == g) s += v;
    }
    int gprev = __shfl_up_sync(0xffffffffu, g, 1);
    bool head = (lane == 0) || (gprev != g);
    if (valid && head) atomicAdd(out + g, s);
}

// -----------------------------------------------------------------------------
// Launch
// Inputs (metadata order): x, edge_index, edge_attr, batch,
//   We1, be1, root1, b1, We2, be2, root2, b2, Wlast, blast
// -----------------------------------------------------------------------------
extern "C" void kernel_launch(void* const* d_in, const int* in_sizes, int n_in,
                              void* d_out, int out_size)
{
    const float* x     = (const float*)d_in[0];
    const int*   ei    = (const int*)  d_in[1];
    const float* ea    = (const float*)d_in[2];
    const int*   batch = (const int*)  d_in[3];
    const float* We1   = (const float*)d_in[4];
    const float* be1   = (const float*)d_in[5];
    const float* root1 = (const float*)d_in[6];
    const float* b1    = (const float*)d_in[7];
    const float* We2   = (const float*)d_in[8];
    const float* be2   = (const float*)d_in[9];
    const float* root2 = (const float*)d_in[10];
    const float* b2    = (const float*)d_in[11];
    const float* Wlast = (const float*)d_in[12];
    const float* blast = (const float*)d_in[13];
    float* out = (float*)d_out;

    const int N = in_sizes[0] / 16;   // 50000
    const int E = in_sizes[1] / 2;    // 800000
    const int G = out_size;           // 512

    float *pP = nullptr, *pA1 = nullptr, *pA2 = nullptr;
    cudaGetSymbolAddress((void**)&pP,  g_P);
    cudaGetSymbolAddress((void**)&pA1, g_agg1);
    cudaGetSymbolAddress((void**)&pA2, g_agg2);

    const int TB = 256;
    const int nodeGrid = (N * 8 + TB - 1) / TB;
    const int edgeGrid = (E + TB - 1) / TB;

    // Layer 1
    node_prep_kernel<16, false><<<nodeGrid, TB>>>(x, We1, be1, root1, b1, pP, pA1, N);
    edge_kernel<<<edgeGrid, TB>>>(ei, ea, pP, pA1, E);
    // Layer 2 (relu of agg1 inside node_prep)
    node_prep_kernel<8, true><<<nodeGrid, TB>>>(pA1, We2, be2, root2, b2, pP, pA2, N);
    edge_kernel<<<edgeGrid, TB>>>(ei, ea, pP, pA2, E);
    // Pool + readout
    init_out_kernel<<<(G + TB - 1) / TB, TB>>>(out, blast, G);
    pool_kernel<<<(N + TB - 1) / TB, TB>>>(pA2, batch, Wlast, out, N);
}

// round 2
// speedup vs baseline: 1.4134x; 1.4134x over previous
#include <cuda_runtime.h>
#include <cuda_bf16.h>
#include <cstdint>

// Problem constants (from reference setup_inputs)
#define MAXN 50000
#define MAXE 800000
#define NGRAPH 512

// Scratch (device globals: allocation-free).
// g_P is reused by both layers: [N, 72] = [N][k=0..7 rows of 8][bias row of 8]
__device__ __align__(128) float g_P[(size_t)MAXN * 72];
__device__ __align__(128) float g_agg1[(size_t)MAXN * 8];
__device__ __align__(128) float g_agg2[(size_t)MAXN * 8];

// -----------------------------------------------------------------------------
// Node precompute: P[n,k,o] = sum_i in[n,i] * We[k, i*8+o]
//                  P[n,8,o] = sum_i in[n,i] * be[i*8+o]   (bias row)
//                  agg[n,o] = b[o] + sum_i in[n,i] * root[i,o]  (root init)
// One thread per (node, o). RELU applied to input when templated on.
// -----------------------------------------------------------------------------
template<int IN, bool RELU>
__global__ void node_prep_kernel(
    const float* __restrict__ xin,   // [N, IN] (pre-activation if RELU)
    const float* __restrict__ We,    // [8, IN*8]
    const float* __restrict__ be,    // [IN*8]
    const float* __restrict__ root,  // [IN, 8]
    const float* __restrict__ bvec,  // [8]
    float* __restrict__ P,           // [N, 72]
    float* __restrict__ agg,         // [N, 8]
    int N)
{
    __shared__ float sW[8 * IN * 8];
    __shared__ float sB[IN * 8];
    __shared__ float sR[IN * 8];
    __shared__ float sb[8];
    for (int i = threadIdx.x; i < 8 * IN * 8; i += blockDim.x) sW[i] = We[i];
    for (int i = threadIdx.x; i < IN * 8; i += blockDim.x) { sB[i] = be[i]; sR[i] = root[i]; }
    if (threadIdx.x < 8) sb[threadIdx.x] = bvec[threadIdx.x];
    __syncthreads();

    int idx = blockIdx.x * blockDim.x + threadIdx.x;
    int n = idx >> 3;
    int o = idx & 7;
    if (n >= N) return;

    float xv[IN];
#pragma unroll
    for (int i = 0; i < IN; i++) {
        float v = __ldg(xin + (size_t)n * IN + i);
        xv[i] = RELU ? fmaxf(v, 0.0f) : v;
    }

    float* Pr = P + (size_t)n * 72;
#pragma unroll
    for (int k = 0; k < 8; k++) {
        float acc = 0.0f;
#pragma unroll
        for (int i = 0; i < IN; i++) acc = fmaf(xv[i], sW[k * IN * 8 + i * 8 + o], acc);
        Pr[k * 8 + o] = acc;
    }
    float accb = 0.0f;
#pragma unroll
    for (int i = 0; i < IN; i++) accb = fmaf(xv[i], sB[i * 8 + o], accb);
    Pr[64 + o] = accb;

    float accr = sb[o];
#pragma unroll
    for (int i = 0; i < IN; i++) accr = fmaf(xv[i], sR[i * 8 + o], accr);
    agg[(size_t)n * 8 + o] = accr;
}

// -----------------------------------------------------------------------------
// Edge phase (cooperative, 8 threads per edge):
//   thread o computes msg[o] = P[src,8,o] + sum_k ea[e,k] * P[src,k,o]
// Per k, the 8 lanes of a group read one fully-used 32B sector of P (coalesced).
// ea coefficients distributed via width-8 shuffles. Messages repacked so lanes
// with (o%4)==0 issue red.v4 (2 REDs per edge).
// -----------------------------------------------------------------------------
__global__ void edge_kernel(
    const int*   __restrict__ ei,   // [2, E] (src row, dst row)
    const float* __restrict__ ea,   // [E, 8]
    const float* __restrict__ P,    // [N, 72]
    float*       __restrict__ agg,  // [N, 8]
    int E)
{
    int t = blockIdx.x * blockDim.x + threadIdx.x;
    int e = t >> 3;
    int o = t & 7;
    if (e >= E) return;

    int src = __ldg(ei + e);

    float myea = __ldg(ea + (size_t)e * 8 + o);      // 32B coalesced per edge

    const float* p = P + (size_t)src * 72 + o;
    float m = __ldg(p + 64);                          // bias row
#pragma unroll
    for (int k = 0; k < 8; k++) {
        float c = __shfl_sync(0xffffffffu, myea, k, 8);
        m = fmaf(c, __ldg(p + k * 8), m);             // one 32B sector per group per k
    }

    // Repack: lane o in {0,4} of each group gathers m from o+1, o+2, o+3.
    float y1 = __shfl_sync(0xffffffffu, m, o + 1, 8);
    float y2 = __shfl_sync(0xffffffffu, m, o + 2, 8);
    float y3 = __shfl_sync(0xffffffffu, m, o + 3, 8);

    if ((o & 3) == 0) {
        int dst = __ldg(ei + E + e);
        float* outp = agg + (size_t)dst * 8 + o;
        asm volatile("red.relaxed.gpu.global.add.v4.f32 [%0], {%1,%2,%3,%4};"
                     :: "l"(outp), "f"(m), "f"(y1), "f"(y2), "f"(y3) : "memory");
    }
}

// -----------------------------------------------------------------------------
// Output init: out[g] = blast[0]
// -----------------------------------------------------------------------------
__global__ void init_out_kernel(float* __restrict__ out, const float* __restrict__ blast, int G)
{
    int i = blockIdx.x * blockDim.x + threadIdx.x;
    if (i < G) out[i] = __ldg(blast);
}

// -----------------------------------------------------------------------------
// Pool + readout: out[batch[n]] += relu(agg2[n]) . Wlast
// batch is sorted -> warp-segmented reduction before atomics.
// -----------------------------------------------------------------------------
__global__ void pool_kernel(
    const float* __restrict__ agg2,
    const int*   __restrict__ batch,
    const float* __restrict__ Wlast,  // [8]
    float*       __restrict__ out,    // [G]
    int N)
{
    int n = blockIdx.x * blockDim.x + threadIdx.x;
    int lane = threadIdx.x & 31;
    bool valid = (n < N);
    float s = 0.0f;
    int g = -1;
    if (valid) {
        g = __ldg(batch + n);
#pragma unroll
        for (int o = 0; o < 8; o++) {
            float h = fmaxf(__ldg(agg2 + (size_t)n * 8 + o), 0.0f);
            s = fmaf(h, __ldg(Wlast + o), s);
        }
    }
    // segmented suffix-sum over sorted keys within a warp
#pragma unroll
    for (int d = 1; d < 32; d <<= 1) {
        float v = __shfl_down_sync(0xffffffffu, s, d);
        int gg   = __shfl_down_sync(0xffffffffu, g, d);
        if (lane + d < 32 && gg == g) s += v;
    }
    int gprev = __shfl_up_sync(0xffffffffu, g, 1);
    bool head = (lane == 0) || (gprev != g);
    if (valid && head) atomicAdd(out + g, s);
}

// -----------------------------------------------------------------------------
// Launch
// Inputs (metadata order): x, edge_index, edge_attr, batch,
//   We1, be1, root1, b1, We2, be2, root2, b2, Wlast, blast
// -----------------------------------------------------------------------------
extern "C" void kernel_launch(void* const* d_in, const int* in_sizes, int n_in,
                              void* d_out, int out_size)
{
    const float* x     = (const float*)d_in[0];
    const int*   ei    = (const int*)  d_in[1];
    const float* ea    = (const float*)d_in[2];
    const int*   batch = (const int*)  d_in[3];
    const float* We1   = (const float*)d_in[4];
    const float* be1   = (const float*)d_in[5];
    const float* root1 = (const float*)d_in[6];
    const float* b1    = (const float*)d_in[7];
    const float* We2   = (const float*)d_in[8];
    const float* be2   = (const float*)d_in[9];
    const float* root2 = (const float*)d_in[10];
    const float* b2    = (const float*)d_in[11];
    const float* Wlast = (const float*)d_in[12];
    const float* blast = (const float*)d_in[13];
    float* out = (float*)d_out;

    const int N = in_sizes[0] / 16;   // 50000
    const int E = in_sizes[1] / 2;    // 800000
    const int G = out_size;           // 512

    float *pP = nullptr, *pA1 = nullptr, *pA2 = nullptr;
    cudaGetSymbolAddress((void**)&pP,  g_P);
    cudaGetSymbolAddress((void**)&pA1, g_agg1);
    cudaGetSymbolAddress((void**)&pA2, g_agg2);

    const int TB = 256;
    const int nodeGrid = (N * 8 + TB - 1) / TB;
    const int edgeGrid = ((E * 8) + TB - 1) / TB;

    // Layer 1
    node_prep_kernel<16, false><<<nodeGrid, TB>>>(x, We1, be1, root1, b1, pP, pA1, N);
    edge_kernel<<<edgeGrid, TB>>>(ei, ea, pP, pA1, E);
    // Layer 2 (relu of agg1 inside node_prep)
    node_prep_kernel<8, true><<<nodeGrid, TB>>>(pA1, We2, be2, root2, b2, pP, pA2, N);
    edge_kernel<<<edgeGrid, TB>>>(ei, ea, pP, pA2, E);
    // Pool + readout
    init_out_kernel<<<(G + TB - 1) / TB, TB>>>(out, blast, G);
    pool_kernel<<<(N + TB - 1) / TB, TB>>>(pA2, batch, Wlast, out, N);
}

// round 3
// speedup vs baseline: 1.6729x; 1.1836x over previous
#include <cuda_runtime.h>
#include <cuda_fp16.h>
#include <cstdint>

// Problem constants (from reference setup_inputs)
#define MAXN 50000
#define MAXE 800000
#define NGRAPH 512

// Scratch (device globals: allocation-free).
// g_P16: [N][40] half2 = 160B/row:
//   chunk kk (kk=0..3) at [kk*8+o]: half2{ P[k=2kk][o], P[k=2kk+1][o] }
//   bias chunk at [32+o]:           half2{ bias[o], 0 }
__device__ __align__(128) __half2 g_P16[(size_t)MAXN * 40];
__device__ __align__(128) float g_agg1[(size_t)MAXN * 8];
__device__ __align__(128) float g_agg2[(size_t)MAXN * 8];

// -----------------------------------------------------------------------------
// Node precompute: P[n,k,o] = sum_i in[n,i] * We[k, i*8+o]  (stored fp16 packed)
//                  bias[n,o] = sum_i in[n,i] * be[i*8+o]
//                  agg[n,o] = b[o] + sum_i in[n,i] * root[i,o]  (fp32 root init)
// One thread per (node, o). RELU applied to input when templated on.
// -----------------------------------------------------------------------------
template<int IN, bool RELU>
__global__ void node_prep_kernel(
    const float* __restrict__ xin,   // [N, IN] (pre-activation if RELU)
    const float* __restrict__ We,    // [8, IN*8]
    const float* __restrict__ be,    // [IN*8]
    const float* __restrict__ root,  // [IN, 8]
    const float* __restrict__ bvec,  // [8]
    __half2* __restrict__ P,         // [N, 40]
    float* __restrict__ agg,         // [N, 8]
    int N)
{
    __shared__ float sW[8 * IN * 8];
    __shared__ float sB[IN * 8];
    __shared__ float sR[IN * 8];
    __shared__ float sb[8];
    for (int i = threadIdx.x; i < 8 * IN * 8; i += blockDim.x) sW[i] = We[i];
    for (int i = threadIdx.x; i < IN * 8; i += blockDim.x) { sB[i] = be[i]; sR[i] = root[i]; }
    if (threadIdx.x < 8) sb[threadIdx.x] = bvec[threadIdx.x];
    __syncthreads();

    int idx = blockIdx.x * blockDim.x + threadIdx.x;
    int n = idx >> 3;
    int o = idx & 7;
    if (n >= N) return;

    float xv[IN];
#pragma unroll
    for (int i = 0; i < IN; i++) {
        float v = __ldg(xin + (size_t)n * IN + i);
        xv[i] = RELU ? fmaxf(v, 0.0f) : v;
    }

    float acc[8];
#pragma unroll
    for (int k = 0; k < 8; k++) {
        float a = 0.0f;
#pragma unroll
        for (int i = 0; i < IN; i++) a = fmaf(xv[i], sW[k * IN * 8 + i * 8 + o], a);
        acc[k] = a;
    }
    float accb = 0.0f;
#pragma unroll
    for (int i = 0; i < IN; i++) accb = fmaf(xv[i], sB[i * 8 + o], accb);

    __half2* Pr = P + (size_t)n * 40;
#pragma unroll
    for (int kk = 0; kk < 4; kk++)
        Pr[kk * 8 + o] = __floats2half2_rn(acc[2 * kk], acc[2 * kk + 1]);
    Pr[32 + o] = __floats2half2_rn(accb, 0.0f);

    float accr = sb[o];
#pragma unroll
    for (int i = 0; i < IN; i++) accr = fmaf(xv[i], sR[i * 8 + o], accr);
    agg[(size_t)n * 8 + o] = accr;
}

// -----------------------------------------------------------------------------
// Edge phase (cooperative, 8 threads per edge):
//   thread o computes msg[o] = bias[src,o] + sum_k ea[e,k] * P[src,k,o]
// P is fp16 packed in k-pairs: 4 gather LDG.32 + 1 bias LDG.32 per thread;
// each warp load touches one fully-used 32B sector per edge-group.
// fp32 accumulate; messages repacked so lanes with (o%4)==0 issue red.v4.
// -----------------------------------------------------------------------------
__global__ void edge_kernel(
    const int*     __restrict__ ei,   // [2, E] (src row, dst row)
    const float*   __restrict__ ea,   // [E, 8]
    const __half2* __restrict__ P,    // [N, 40]
    float*         __restrict__ agg,  // [N, 8]
    int E)
{
    int t = blockIdx.x * blockDim.x + threadIdx.x;
    int e = t >> 3;
    int o = t & 7;
    if (e >= E) return;

    int src = __ldg(ei + e);
    float myea = __ldg(ea + (size_t)e * 8 + o);      // 32B coalesced per edge

    const __half2* p = P + (size_t)src * 40 + o;
    float m = __half2float(__low2half(__ldg(p + 32)));   // bias
#pragma unroll
    for (int kk = 0; kk < 4; kk++) {
        float c0 = __shfl_sync(0xffffffffu, myea, 2 * kk, 8);
        float c1 = __shfl_sync(0xffffffffu, myea, 2 * kk + 1, 8);
        float2 pv = __half22float2(__ldg(p + kk * 8));   // one 32B sector / group
        m = fmaf(c0, pv.x, m);
        m = fmaf(c1, pv.y, m);
    }

    // Repack: lane o in {0,4} of each group gathers m from o+1, o+2, o+3.
    float y1 = __shfl_sync(0xffffffffu, m, o + 1, 8);
    float y2 = __shfl_sync(0xffffffffu, m, o + 2, 8);
    float y3 = __shfl_sync(0xffffffffu, m, o + 3, 8);

    if ((o & 3) == 0) {
        int dst = __ldg(ei + E + e);
        float* outp = agg + (size_t)dst * 8 + o;
        asm volatile("red.relaxed.gpu.global.add.v4.f32 [%0], {%1,%2,%3,%4};"
                     :: "l"(outp), "f"(m), "f"(y1), "f"(y2), "f"(y3) : "memory");
    }
}

// -----------------------------------------------------------------------------
// Output init: out[g] = blast[0]
// -----------------------------------------------------------------------------
__global__ void init_out_kernel(float* __restrict__ out, const float* __restrict__ blast, int G)
{
    int i = blockIdx.x * blockDim.x + threadIdx.x;
    if (i < G) out[i] = __ldg(blast);
}

// -----------------------------------------------------------------------------
// Pool + readout: out[batch[n]] += relu(agg2[n]) . Wlast
// batch is sorted -> warp-segmented reduction before atomics.
// -----------------------------------------------------------------------------
__global__ void pool_kernel(
    const float* __restrict__ agg2,
    const int*   __restrict__ batch,
    const float* __restrict__ Wlast,  // [8]
    float*       __restrict__ out,    // [G]
    int N)
{
    int n = blockIdx.x * blockDim.x + threadIdx.x;
    int lane = threadIdx.x & 31;
    bool valid = (n < N);
    float s = 0.0f;
    int g = -1;
    if (valid) {
        g = __ldg(batch + n);
#pragma unroll
        for (int o = 0; o < 8; o++) {
            float h = fmaxf(__ldg(agg2 + (size_t)n * 8 + o), 0.0f);
            s = fmaf(h, __ldg(Wlast + o), s);
        }
    }
    // segmented suffix-sum over sorted keys within a warp
#pragma unroll
    for (int d = 1; d < 32; d <<= 1) {
        float v = __shfl_down_sync(0xffffffffu, s, d);
        int gg   = __shfl_down_sync(0xffffffffu, g, d);
        if (lane + d < 32 && gg == g) s += v;
    }
    int gprev = __shfl_up_sync(0xffffffffu, g, 1);
    bool head = (lane == 0) || (gprev != g);
    if (valid && head) atomicAdd(out + g, s);
}

// -----------------------------------------------------------------------------
// Launch
// Inputs (metadata order): x, edge_index, edge_attr, batch,
//   We1, be1, root1, b1, We2, be2, root2, b2, Wlast, blast
// -----------------------------------------------------------------------------
extern "C" void kernel_launch(void* const* d_in, const int* in_sizes, int n_in,
                              void* d_out, int out_size)
{
    const float* x     = (const float*)d_in[0];
    const int*   ei    = (const int*)  d_in[1];
    const float* ea    = (const float*)d_in[2];
    const int*   batch = (const int*)  d_in[3];
    const float* We1   = (const float*)d_in[4];
    const float* be1   = (const float*)d_in[5];
    const float* root1 = (const float*)d_in[6];
    const float* b1    = (const float*)d_in[7];
    const float* We2   = (const float*)d_in[8];
    const float* be2   = (const float*)d_in[9];
    const float* root2 = (const float*)d_in[10];
    const float* b2    = (const float*)d_in[11];
    const float* Wlast = (const float*)d_in[12];
    const float* blast = (const float*)d_in[13];
    float* out = (float*)d_out;

    const int N = in_sizes[0] / 16;   // 50000
    const int E = in_sizes[1] / 2;    // 800000
    const int G = out_size;           // 512

    __half2* pP = nullptr;
    float *pA1 = nullptr, *pA2 = nullptr;
    cudaGetSymbolAddress((void**)&pP,  g_P16);
    cudaGetSymbolAddress((void**)&pA1, g_agg1);
    cudaGetSymbolAddress((void**)&pA2, g_agg2);

    const int TB = 256;
    const int nodeGrid = (N * 8 + TB - 1) / TB;
    const int edgeGrid = ((E * 8) + TB - 1) / TB;

    // Layer 1
    node_prep_kernel<16, false><<<nodeGrid, TB>>>(x, We1, be1, root1, b1, pP, pA1, N);
    edge_kernel<<<edgeGrid, TB>>>(ei, ea, pP, pA1, E);
    // Layer 2 (relu of agg1 inside node_prep)
    node_prep_kernel<8, true><<<nodeGrid, TB>>>(pA1, We2, be2, root2, b2, pP, pA2, N);
    edge_kernel<<<edgeGrid, TB>>>(ei, ea, pP, pA2, E);
    // Pool + readout
    init_out_kernel<<<(G + TB - 1) / TB, TB>>>(out, blast, G);
    pool_kernel<<<(N + TB - 1) / TB, TB>>>(pA2, batch, Wlast, out, N);
}

// round 4
// speedup vs baseline: 1.8425x; 1.1013x over previous
#include <cuda_runtime.h>
#include <cuda_fp16.h>
#include <cstdint>

// Problem constants (from reference setup_inputs)
#define MAXN 50000
#define MAXE 800000
#define NGRAPH 512

// Scratch (device globals: allocation-free).
// g_Pmain: [N][64] half, 128B per row, 128B aligned.
//   half at [n*64 + o*8 + k] = P[n,k,o]  (lane o reads one uint4 = all 8 k's)
// g_Pbias: [N][8] half: bias term per (n,o)
__device__ __align__(128) __half g_Pmain[(size_t)MAXN * 64];
__device__ __align__(128) __half g_Pbias[(size_t)MAXN * 8];
__device__ __align__(128) float g_agg1[(size_t)MAXN * 8];
__device__ __align__(128) float g_agg2[(size_t)MAXN * 8];

// -----------------------------------------------------------------------------
// Node precompute: Pmain[n,o,k] = sum_i in[n,i] * We[k, i*8+o]   (fp16, transposed)
//                  Pbias[n,o]   = sum_i in[n,i] * be[i*8+o]
//                  agg[n,o] = b[o] + sum_i in[n,i] * root[i,o]   (fp32 root init)
// One thread per (node, o). RELU applied to input when templated on.
// -----------------------------------------------------------------------------
template<int IN, bool RELU>
__global__ void node_prep_kernel(
    const float* __restrict__ xin,   // [N, IN] (pre-activation if RELU)
    const float* __restrict__ We,    // [8, IN*8]
    const float* __restrict__ be,    // [IN*8]
    const float* __restrict__ root,  // [IN, 8]
    const float* __restrict__ bvec,  // [8]
    __half* __restrict__ Pmain,      // [N, 64]
    __half* __restrict__ Pbias,      // [N, 8]
    float* __restrict__ agg,         // [N, 8]
    int N)
{
    __shared__ float sW[8 * IN * 8];
    __shared__ float sB[IN * 8];
    __shared__ float sR[IN * 8];
    __shared__ float sb[8];
    for (int i = threadIdx.x; i < 8 * IN * 8; i += blockDim.x) sW[i] = We[i];
    for (int i = threadIdx.x; i < IN * 8; i += blockDim.x) { sB[i] = be[i]; sR[i] = root[i]; }
    if (threadIdx.x < 8) sb[threadIdx.x] = bvec[threadIdx.x];
    __syncthreads();

    int idx = blockIdx.x * blockDim.x + threadIdx.x;
    int n = idx >> 3;
    int o = idx & 7;
    if (n >= N) return;

    float xv[IN];
#pragma unroll
    for (int i = 0; i < IN; i++) {
        float v = __ldg(xin + (size_t)n * IN + i);
        xv[i] = RELU ? fmaxf(v, 0.0f) : v;
    }

    // All 8 k-values for this (n, o): exactly lane o's 16B chunk.
    __half2 packed[4];
#pragma unroll
    for (int kk = 0; kk < 4; kk++) {
        float a0 = 0.0f, a1 = 0.0f;
#pragma unroll
        for (int i = 0; i < IN; i++) {
            a0 = fmaf(xv[i], sW[(2 * kk)     * IN * 8 + i * 8 + o], a0);
            a1 = fmaf(xv[i], sW[(2 * kk + 1) * IN * 8 + i * 8 + o], a1);
        }
        packed[kk] = __floats2half2_rn(a0, a1);
    }
    *reinterpret_cast<uint4*>(Pmain + (size_t)n * 64 + o * 8) =
        *reinterpret_cast<uint4*>(packed);

    float accb = 0.0f;
#pragma unroll
    for (int i = 0; i < IN; i++) accb = fmaf(xv[i], sB[i * 8 + o], accb);
    Pbias[(size_t)n * 8 + o] = __float2half_rn(accb);

    float accr = sb[o];
#pragma unroll
    for (int i = 0; i < IN; i++) accr = fmaf(xv[i], sR[i * 8 + o], accr);
    agg[(size_t)n * 8 + o] = accr;
}

// -----------------------------------------------------------------------------
// Edge phase (cooperative, 8 threads per edge):
//   thread o computes msg[o] = Pbias[src,o] + sum_k ea[e,k] * Pmain[src,o,k]
// Gather: ONE LDG.128 per thread hits one 128B-aligned line per edge-group
// (1 wavefront/edge) + one tiny bias load. Coefficients via width-8 shuffles.
// fp32 accumulate; messages repacked so lanes with (o%4)==0 issue red.v4.
// -----------------------------------------------------------------------------
__global__ void edge_kernel(
    const int*    __restrict__ ei,     // [2, E] (src row, dst row)
    const float*  __restrict__ ea,     // [E, 8]
    const __half* __restrict__ Pmain,  // [N, 64]
    const __half* __restrict__ Pbias,  // [N, 8]
    float*        __restrict__ agg,    // [N, 8]
    int E)
{
    int t = blockIdx.x * blockDim.x + threadIdx.x;
    int e = t >> 3;
    int o = t & 7;
    if (e >= E) return;

    int src = __ldg(ei + e);
    float myea = __ldg(ea + (size_t)e * 8 + o);      // 32B coalesced per edge

    // One 16B load: all 8 k-values for this lane's output channel.
    uint4 raw = __ldg(reinterpret_cast<const uint4*>(Pmain + (size_t)src * 64 + o * 8));
    __half2 ph[4];
    *reinterpret_cast<uint4*>(ph) = raw;

    float m = __half2float(__ldg(Pbias + (size_t)src * 8 + o));
#pragma unroll
    for (int kk = 0; kk < 4; kk++) {
        float c0 = __shfl_sync(0xffffffffu, myea, 2 * kk, 8);
        float c1 = __shfl_sync(0xffffffffu, myea, 2 * kk + 1, 8);
        float2 pv = __half22float2(ph[kk]);
        m = fmaf(c0, pv.x, m);
        m = fmaf(c1, pv.y, m);
    }

    // Repack: lane o in {0,4} of each group gathers m from o+1, o+2, o+3.
    float y1 = __shfl_sync(0xffffffffu, m, o + 1, 8);
    float y2 = __shfl_sync(0xffffffffu, m, o + 2, 8);
    float y3 = __shfl_sync(0xffffffffu, m, o + 3, 8);

    if ((o & 3) == 0) {
        int dst = __ldg(ei + E + e);
        float* outp = agg + (size_t)dst * 8 + o;
        asm volatile("red.relaxed.gpu.global.add.v4.f32 [%0], {%1,%2,%3,%4};"
                     :: "l"(outp), "f"(m), "f"(y1), "f"(y2), "f"(y3) : "memory");
    }
}

// -----------------------------------------------------------------------------
// Output init: out[g] = blast[0]
// -----------------------------------------------------------------------------
__global__ void init_out_kernel(float* __restrict__ out, const float* __restrict__ blast, int G)
{
    int i = blockIdx.x * blockDim.x + threadIdx.x;
    if (i < G) out[i] = __ldg(blast);
}

// -----------------------------------------------------------------------------
// Pool + readout: out[batch[n]] += relu(agg2[n]) . Wlast
// batch is sorted -> warp-segmented reduction before atomics.
// -----------------------------------------------------------------------------
__global__ void pool_kernel(
    const float* __restrict__ agg2,
    const int*   __restrict__ batch,
    const float* __restrict__ Wlast,  // [8]
    float*       __restrict__ out,    // [G]
    int N)
{
    int n = blockIdx.x * blockDim.x + threadIdx.x;
    int lane = threadIdx.x & 31;
    bool valid = (n < N);
    float s = 0.0f;
    int g = -1;
    if (valid) {
        g = __ldg(batch + n);
#pragma unroll
        for (int o = 0; o < 8; o++) {
            float h = fmaxf(__ldg(agg2 + (size_t)n * 8 + o), 0.0f);
            s = fmaf(h, __ldg(Wlast + o), s);
        }
    }
    // segmented suffix-sum over sorted keys within a warp
#pragma unroll
    for (int d = 1; d < 32; d <<= 1) {
        float v = __shfl_down_sync(0xffffffffu, s, d);
        int gg   = __shfl_down_sync(0xffffffffu, g, d);
        if (lane + d < 32 && gg == g) s += v;
    }
    int gprev = __shfl_up_sync(0xffffffffu, g, 1);
    bool head = (lane == 0) || (gprev != g);
    if (valid && head) atomicAdd(out + g, s);
}

// -----------------------------------------------------------------------------
// Launch
// Inputs (metadata order): x, edge_index, edge_attr, batch,
//   We1, be1, root1, b1, We2, be2, root2, b2, Wlast, blast
// -----------------------------------------------------------------------------
extern "C" void kernel_launch(void* const* d_in, const int* in_sizes, int n_in,
                              void* d_out, int out_size)
{
    const float* x     = (const float*)d_in[0];
    const int*   ei    = (const int*)  d_in[1];
    const float* ea    = (const float*)d_in[2];
    const int*   batch = (const int*)  d_in[3];
    const float* We1   = (const float*)d_in[4];
    const float* be1   = (const float*)d_in[5];
    const float* root1 = (const float*)d_in[6];
    const float* b1    = (const float*)d_in[7];
    const float* We2   = (const float*)d_in[8];
    const float* be2   = (const float*)d_in[9];
    const float* root2 = (const float*)d_in[10];
    const float* b2    = (const float*)d_in[11];
    const float* Wlast = (const float*)d_in[12];
    const float* blast = (const float*)d_in[13];
    float* out = (float*)d_out;

    const int N = in_sizes[0] / 16;   // 50000
    const int E = in_sizes[1] / 2;    // 800000
    const int G = out_size;           // 512

    __half *pPm = nullptr, *pPb = nullptr;
    float *pA1 = nullptr, *pA2 = nullptr;
    cudaGetSymbolAddress((void**)&pPm, g_Pmain);
    cudaGetSymbolAddress((void**)&pPb, g_Pbias);
    cudaGetSymbolAddress((void**)&pA1, g_agg1);
    cudaGetSymbolAddress((void**)&pA2, g_agg2);

    const int TB = 256;
    const int nodeGrid = (N * 8 + TB - 1) / TB;
    const int edgeGrid = ((E * 8) + TB - 1) / TB;

    // Layer 1
    node_prep_kernel<16, false><<<nodeGrid, TB>>>(x, We1, be1, root1, b1, pPm, pPb, pA1, N);
    edge_kernel<<<edgeGrid, TB>>>(ei, ea, pPm, pPb, pA1, E);
    // Layer 2 (relu of agg1 inside node_prep)
    node_prep_kernel<8, true><<<nodeGrid, TB>>>(pA1, We2, be2, root2, b2, pPm, pPb, pA2, N);
    edge_kernel<<<edgeGrid, TB>>>(ei, ea, pPm, pPb, pA2, E);
    // Pool + readout
    init_out_kernel<<<(G + TB - 1) / TB, TB>>>(out, blast, G);
    pool_kernel<<<(N + TB - 1) / TB, TB>>>(pA2, batch, Wlast, out, N);
}

// round 5
// speedup vs baseline: 2.0619x; 1.1191x over previous
#include <cuda_runtime.h>
#include <cuda_fp16.h>
#include <cstdint>

// Problem constants (from reference setup_inputs)
#define MAXN 50000
#define MAXE 800000
#define NGRAPH 512

// Scratch (device globals: allocation-free).
// g_Pmain: [N][64] half, 128B per row, 128B aligned.
//   half at [n*64 + o*8 + k] = P[n,k,o]  (lane o reads one uint4 = all 8 k's)
// g_Pbias: [N][8] half: bias term per (n,o)
__device__ __align__(128) __half g_Pmain[(size_t)MAXN * 64];
__device__ __align__(128) __half g_Pbias[(size_t)MAXN * 8];
__device__ __align__(128) float g_agg1[(size_t)MAXN * 8];
__device__ __align__(128) float g_agg2[(size_t)MAXN * 8];

// -----------------------------------------------------------------------------
// Node precompute: Pmain[n,o,k] = sum_i in[n,i] * We[k, i*8+o]   (fp16, transposed)
//                  Pbias[n,o]   = sum_i in[n,i] * be[i*8+o]
//                  agg[n,o] = b[o] + sum_i in[n,i] * root[i,o]   (fp32 root init)
// One thread per (node, o). RELU applied to input when templated on.
// -----------------------------------------------------------------------------
template<int IN, bool RELU>
__global__ void node_prep_kernel(
    const float* __restrict__ xin,   // [N, IN] (pre-activation if RELU)
    const float* __restrict__ We,    // [8, IN*8]
    const float* __restrict__ be,    // [IN*8]
    const float* __restrict__ root,  // [IN, 8]
    const float* __restrict__ bvec,  // [8]
    __half* __restrict__ Pmain,      // [N, 64]
    __half* __restrict__ Pbias,      // [N, 8]
    float* __restrict__ agg,         // [N, 8]
    int N)
{
    __shared__ float sW[8 * IN * 8];
    __shared__ float sB[IN * 8];
    __shared__ float sR[IN * 8];
    __shared__ float sb[8];
    for (int i = threadIdx.x; i < 8 * IN * 8; i += blockDim.x) sW[i] = We[i];
    for (int i = threadIdx.x; i < IN * 8; i += blockDim.x) { sB[i] = be[i]; sR[i] = root[i]; }
    if (threadIdx.x < 8) sb[threadIdx.x] = bvec[threadIdx.x];
    __syncthreads();

    int idx = blockIdx.x * blockDim.x + threadIdx.x;
    int n = idx >> 3;
    int o = idx & 7;
    if (n >= N) return;

    float xv[IN];
#pragma unroll
    for (int i = 0; i < IN; i++) {
        float v = __ldg(xin + (size_t)n * IN + i);
        xv[i] = RELU ? fmaxf(v, 0.0f) : v;
    }

    // All 8 k-values for this (n, o): exactly lane o's 16B chunk.
    __half2 packed[4];
#pragma unroll
    for (int kk = 0; kk < 4; kk++) {
        float a0 = 0.0f, a1 = 0.0f;
#pragma unroll
        for (int i = 0; i < IN; i++) {
            a0 = fmaf(xv[i], sW[(2 * kk)     * IN * 8 + i * 8 + o], a0);
            a1 = fmaf(xv[i], sW[(2 * kk + 1) * IN * 8 + i * 8 + o], a1);
        }
        packed[kk] = __floats2half2_rn(a0, a1);
    }
    *reinterpret_cast<uint4*>(Pmain + (size_t)n * 64 + o * 8) =
        *reinterpret_cast<uint4*>(packed);

    float accb = 0.0f;
#pragma unroll
    for (int i = 0; i < IN; i++) accb = fmaf(xv[i], sB[i * 8 + o], accb);
    Pbias[(size_t)n * 8 + o] = __float2half_rn(accb);

    float accr = sb[o];
#pragma unroll
    for (int i = 0; i < IN; i++) accr = fmaf(xv[i], sR[i * 8 + o], accr);
    agg[(size_t)n * 8 + o] = accr;
}

// -----------------------------------------------------------------------------
// Edge phase (cooperative, 8 threads per edge), shuffle-free:
//   thread o: msg = Pbias[src,o] + sum_k ea[e,k] * Pmain[src,o,k]
//   - ea loaded by every lane (2x LDG.128, group-broadcast: 1 line/warp)
//   - P gather: 1x LDG.128, 4 lines/warp (one 128B line per edge)
//   - scatter: full-warp scalar red.f32 (one instruction covers 4 edges x 8 ch)
// -----------------------------------------------------------------------------
__global__ void edge_kernel(
    const int*    __restrict__ ei,     // [2, E] (src row, dst row)
    const float*  __restrict__ ea,     // [E, 8]
    const __half* __restrict__ Pmain,  // [N, 64]
    const __half* __restrict__ Pbias,  // [N, 8]
    float*        __restrict__ agg,    // [N, 8]
    int E)
{
    int t = blockIdx.x * blockDim.x + threadIdx.x;
    int e = t >> 3;
    int o = t & 7;
    if (e >= E) return;

    int src = __ldg(ei + e);          // broadcast within group
    int dst = __ldg(ei + E + e);      // broadcast within group

    const float4* eap = reinterpret_cast<const float4*>(ea + (size_t)e * 8);
    float4 a0 = __ldg(eap);           // group-broadcast, coalesced across warp
    float4 a1 = __ldg(eap + 1);

    // One 16B load: all 8 k-values for this lane's output channel.
    uint4 raw = __ldg(reinterpret_cast<const uint4*>(Pmain + (size_t)src * 64 + o * 8));
    __half2 ph[4];
    *reinterpret_cast<uint4*>(ph) = raw;

    float m = __half2float(__ldg(Pbias + (size_t)src * 8 + o));
    float2 p0 = __half22float2(ph[0]);
    float2 p1 = __half22float2(ph[1]);
    float2 p2 = __half22float2(ph[2]);
    float2 p3 = __half22float2(ph[3]);
    m = fmaf(a0.x, p0.x, m);
    m = fmaf(a0.y, p0.y, m);
    m = fmaf(a0.z, p1.x, m);
    m = fmaf(a0.w, p1.y, m);
    m = fmaf(a1.x, p2.x, m);
    m = fmaf(a1.y, p2.y, m);
    m = fmaf(a1.z, p3.x, m);
    m = fmaf(a1.w, p3.y, m);

    float* outp = agg + (size_t)dst * 8 + o;
    asm volatile("red.relaxed.gpu.global.add.f32 [%0], %1;"
                 :: "l"(outp), "f"(m) : "memory");
}

// -----------------------------------------------------------------------------
// Output init: out[g] = blast[0]
// -----------------------------------------------------------------------------
__global__ void init_out_kernel(float* __restrict__ out, const float* __restrict__ blast, int G)
{
    int i = blockIdx.x * blockDim.x + threadIdx.x;
    if (i < G) out[i] = __ldg(blast);
}

// -----------------------------------------------------------------------------
// Pool + readout: out[batch[n]] += relu(agg2[n]) . Wlast
// batch is sorted -> warp-segmented reduction before atomics.
// -----------------------------------------------------------------------------
__global__ void pool_kernel(
    const float* __restrict__ agg2,
    const int*   __restrict__ batch,
    const float* __restrict__ Wlast,  // [8]
    float*       __restrict__ out,    // [G]
    int N)
{
    int n = blockIdx.x * blockDim.x + threadIdx.x;
    int lane = threadIdx.x & 31;
    bool valid = (n < N);
    float s = 0.0f;
    int g = -1;
    if (valid) {
        g = __ldg(batch + n);
#pragma unroll
        for (int o = 0; o < 8; o++) {
            float h = fmaxf(__ldg(agg2 + (size_t)n * 8 + o), 0.0f);
            s = fmaf(h, __ldg(Wlast + o), s);
        }
    }
    // segmented suffix-sum over sorted keys within a warp
#pragma unroll
    for (int d = 1; d < 32; d <<= 1) {
        float v = __shfl_down_sync(0xffffffffu, s, d);
        int gg   = __shfl_down_sync(0xffffffffu, g, d);
        if (lane + d < 32 && gg == g) s += v;
    }
    int gprev = __shfl_up_sync(0xffffffffu, g, 1);
    bool head = (lane == 0) || (gprev != g);
    if (valid && head) atomicAdd(out + g, s);
}

// -----------------------------------------------------------------------------
// Launch
// Inputs (metadata order): x, edge_index, edge_attr, batch,
//   We1, be1, root1, b1, We2, be2, root2, b2, Wlast, blast
// -----------------------------------------------------------------------------
extern "C" void kernel_launch(void* const* d_in, const int* in_sizes, int n_in,
                              void* d_out, int out_size)
{
    const float* x     = (const float*)d_in[0];
    const int*   ei    = (const int*)  d_in[1];
    const float* ea    = (const float*)d_in[2];
    const int*   batch = (const int*)  d_in[3];
    const float* We1   = (const float*)d_in[4];
    const float* be1   = (const float*)d_in[5];
    const float* root1 = (const float*)d_in[6];
    const float* b1    = (const float*)d_in[7];
    const float* We2   = (const float*)d_in[8];
    const float* be2   = (const float*)d_in[9];
    const float* root2 = (const float*)d_in[10];
    const float* b2    = (const float*)d_in[11];
    const float* Wlast = (const float*)d_in[12];
    const float* blast = (const float*)d_in[13];
    float* out = (float*)d_out;

    const int N = in_sizes[0] / 16;   // 50000
    const int E = in_sizes[1] / 2;    // 800000
    const int G = out_size;           // 512

    __half *pPm = nullptr, *pPb = nullptr;
    float *pA1 = nullptr, *pA2 = nullptr;
    cudaGetSymbolAddress((void**)&pPm, g_Pmain);
    cudaGetSymbolAddress((void**)&pPb, g_Pbias);
    cudaGetSymbolAddress((void**)&pA1, g_agg1);
    cudaGetSymbolAddress((void**)&pA2, g_agg2);

    const int TB = 256;
    const int nodeGrid = (N * 8 + TB - 1) / TB;
    const int edgeGrid = ((E * 8) + TB - 1) / TB;

    // Layer 1
    node_prep_kernel<16, false><<<nodeGrid, TB>>>(x, We1, be1, root1, b1, pPm, pPb, pA1, N);
    edge_kernel<<<edgeGrid, TB>>>(ei, ea, pPm, pPb, pA1, E);
    // Layer 2 (relu of agg1 inside node_prep)
    node_prep_kernel<8, true><<<nodeGrid, TB>>>(pA1, We2, be2, root2, b2, pPm, pPb, pA2, N);
    edge_kernel<<<edgeGrid, TB>>>(ei, ea, pPm, pPb, pA2, E);
    // Pool + readout
    init_out_kernel<<<(G + TB - 1) / TB, TB>>>(out, blast, G);
    pool_kernel<<<(N + TB - 1) / TB, TB>>>(pA2, batch, Wlast, out, N);
}

// round 7
// speedup vs baseline: 2.1288x; 1.0325x over previous
#include <cuda_runtime.h>
#include <cuda_fp16.h>
#include <cstdint>

// Problem constants (from reference setup_inputs)
#define MAXN 50000
#define MAXE 800000
#define NGRAPH 512

// Scratch (device globals: allocation-free).
// g_Pmain: [N][64] half, 128B per row, 128B aligned.
//   half at [n*64 + o*8 + k] = P[n,k,o]  (lane o reads one uint4 = all 8 k's)
// g_Pbias: [N][8] half: bias term per (n,o)
__device__ __align__(128) __half g_Pmain[(size_t)MAXN * 64];
__device__ __align__(128) __half g_Pbias[(size_t)MAXN * 8];
__device__ __align__(128) float g_agg1[(size_t)MAXN * 8];
__device__ __align__(128) float g_agg2[(size_t)MAXN * 8];

// -----------------------------------------------------------------------------
// Node precompute: Pmain[n,o,k] = sum_i in[n,i] * We[k, i*8+o]   (fp16, transposed)
//                  Pbias[n,o]   = sum_i in[n,i] * be[i*8+o]
//                  agg[n,o] = b[o] + sum_i in[n,i] * root[i,o]   (fp32 root init)
// One thread per (node, o). RELU applied to input when templated on.
// -----------------------------------------------------------------------------
template<int IN, bool RELU>
__global__ void node_prep_kernel(
    const float* __restrict__ xin,   // [N, IN] (pre-activation if RELU)
    const float* __restrict__ We,    // [8, IN*8]
    const float* __restrict__ be,    // [IN*8]
    const float* __restrict__ root,  // [IN, 8]
    const float* __restrict__ bvec,  // [8]
    __half* __restrict__ Pmain,      // [N, 64]
    __half* __restrict__ Pbias,      // [N, 8]
    float* __restrict__ agg,         // [N, 8]
    int N)
{
    __shared__ float sW[8 * IN * 8];
    __shared__ float sB[IN * 8];
    __shared__ float sR[IN * 8];
    __shared__ float sb[8];
    for (int i = threadIdx.x; i < 8 * IN * 8; i += blockDim.x) sW[i] = We[i];
    for (int i = threadIdx.x; i < IN * 8; i += blockDim.x) { sB[i] = be[i]; sR[i] = root[i]; }
    if (threadIdx.x < 8) sb[threadIdx.x] = bvec[threadIdx.x];
    __syncthreads();

    int idx = blockIdx.x * blockDim.x + threadIdx.x;
    int n = idx >> 3;
    int o = idx & 7;
    if (n >= N) return;

    float xv[IN];
#pragma unroll
    for (int i = 0; i < IN; i++) {
        float v = __ldg(xin + (size_t)n * IN + i);
        xv[i] = RELU ? fmaxf(v, 0.0f) : v;
    }

    // All 8 k-values for this (n, o): exactly lane o's 16B chunk.
    __half2 packed[4];
#pragma unroll
    for (int kk = 0; kk < 4; kk++) {
        float a0 = 0.0f, a1 = 0.0f;
#pragma unroll
        for (int i = 0; i < IN; i++) {
            a0 = fmaf(xv[i], sW[(2 * kk)     * IN * 8 + i * 8 + o], a0);
            a1 = fmaf(xv[i], sW[(2 * kk + 1) * IN * 8 + i * 8 + o], a1);
        }
        packed[kk] = __floats2half2_rn(a0, a1);
    }
    *reinterpret_cast<uint4*>(Pmain + (size_t)n * 64 + o * 8) =
        *reinterpret_cast<uint4*>(packed);

    float accb = 0.0f;
#pragma unroll
    for (int i = 0; i < IN; i++) accb = fmaf(xv[i], sB[i * 8 + o], accb);
    Pbias[(size_t)n * 8 + o] = __float2half_rn(accb);

    float accr = sb[o];
#pragma unroll
    for (int i = 0; i < IN; i++) accr = fmaf(xv[i], sR[i * 8 + o], accr);
    agg[(size_t)n * 8 + o] = accr;
}

// -----------------------------------------------------------------------------
// Edge phase: 8 threads per GROUP, 2 edges per group (independent chains for MLP).
//   thread o, edge e: msg = Pbias[src,o] + sum_k ea[e,k] * Pmain[src,o,k]
//   - ea loaded by every lane (LDG.128 group-broadcast)
//   - P gather: 1x LDG.128 per edge (one 128B line per edge)
//   - scatter: full-warp scalar red.f32
// -----------------------------------------------------------------------------
__global__ void edge_kernel(
    const int*    __restrict__ ei,     // [2, E] (src row, dst row)
    const float*  __restrict__ ea,     // [E, 8]
    const __half* __restrict__ Pmain,  // [N, 64]
    const __half* __restrict__ Pbias,  // [N, 8]
    float*        __restrict__ agg,    // [N, 8]
    int E)
{
    int t = blockIdx.x * blockDim.x + threadIdx.x;
    int g = t >> 3;
    int o = t & 7;
    int e0 = 2 * g;
    int e1 = 2 * g + 1;
    if (e0 >= E) return;
    bool has1 = (e1 < E);

    // Independent front-batched loads (2 chains)
    int src0 = __ldcs(ei + e0);
    int src1 = has1 ? __ldcs(ei + e1) : 0;
    int dst0 = __ldcs(ei + E + e0);
    int dst1 = has1 ? __ldcs(ei + E + e1) : 0;

    const float4* eap0 = reinterpret_cast<const float4*>(ea + (size_t)e0 * 8);
    const float4* eap1 = reinterpret_cast<const float4*>(ea + (size_t)e1 * 8);
    float4 a00 = __ldcs(eap0);
    float4 a01 = __ldcs(eap0 + 1);
    float4 a10, a11;
    if (has1) { a10 = __ldcs(eap1); a11 = __ldcs(eap1 + 1); }

    uint4 raw0 = __ldg(reinterpret_cast<const uint4*>(Pmain + (size_t)src0 * 64 + o * 8));
    uint4 raw1 = has1 ? __ldg(reinterpret_cast<const uint4*>(Pmain + (size_t)src1 * 64 + o * 8))
                      : make_uint4(0, 0, 0, 0);
    float b0 = __half2float(__ldg(Pbias + (size_t)src0 * 8 + o));
    float b1 = has1 ? __half2float(__ldg(Pbias + (size_t)src1 * 8 + o)) : 0.0f;

    __half2 ph0[4], ph1[4];
    *reinterpret_cast<uint4*>(ph0) = raw0;
    *reinterpret_cast<uint4*>(ph1) = raw1;

    float m0 = b0, m1 = b1;
    {
        float2 q0 = __half22float2(ph0[0]);
        float2 q1 = __half22float2(ph0[1]);
        float2 q2 = __half22float2(ph0[2]);
        float2 q3 = __half22float2(ph0[3]);
        m0 = fmaf(a00.x, q0.x, m0);
        m0 = fmaf(a00.y, q0.y, m0);
        m0 = fmaf(a00.z, q1.x, m0);
        m0 = fmaf(a00.w, q1.y, m0);
        m0 = fmaf(a01.x, q2.x, m0);
        m0 = fmaf(a01.y, q2.y, m0);
        m0 = fmaf(a01.z, q3.x, m0);
        m0 = fmaf(a01.w, q3.y, m0);
    }
    if (has1) {
        float2 q0 = __half22float2(ph1[0]);
        float2 q1 = __half22float2(ph1[1]);
        float2 q2 = __half22float2(ph1[2]);
        float2 q3 = __half22float2(ph1[3]);
        m1 = fmaf(a10.x, q0.x, m1);
        m1 = fmaf(a10.y, q0.y, m1);
        m1 = fmaf(a10.z, q1.x, m1);
        m1 = fmaf(a10.w, q1.y, m1);
        m1 = fmaf(a11.x, q2.x, m1);
        m1 = fmaf(a11.y, q2.y, m1);
        m1 = fmaf(a11.z, q3.x, m1);
        m1 = fmaf(a11.w, q3.y, m1);
    }

    float* outp0 = agg + (size_t)dst0 * 8 + o;
    asm volatile("red.relaxed.gpu.global.add.f32 [%0], %1;"
                 :: "l"(outp0), "f"(m0) : "memory");
    if (has1) {
        float* outp1 = agg + (size_t)dst1 * 8 + o;
        asm volatile("red.relaxed.gpu.global.add.f32 [%0], %1;"
                     :: "l"(outp1), "f"(m1) : "memory");
    }
}

// -----------------------------------------------------------------------------
// Output init: out[g] = blast[0]
// -----------------------------------------------------------------------------
__global__ void init_out_kernel(float* __restrict__ out, const float* __restrict__ blast, int G)
{
    int i = blockIdx.x * blockDim.x + threadIdx.x;
    if (i < G) out[i] = __ldg(blast);
}

// -----------------------------------------------------------------------------
// Pool + readout: out[batch[n]] += relu(agg2[n]) . Wlast
// batch is sorted -> warp-segmented reduction before atomics.
// -----------------------------------------------------------------------------
__global__ void pool_kernel(
    const float* __restrict__ agg2,
    const int*   __restrict__ batch,
    const float* __restrict__ Wlast,  // [8]
    float*       __restrict__ out,    // [G]
    int N)
{
    int n = blockIdx.x * blockDim.x + threadIdx.x;
    int lane = threadIdx.x & 31;
    bool valid = (n < N);
    float s = 0.0f;
    int g = -1;
    if (valid) {
        g = __ldg(batch + n);
#pragma unroll
        for (int o = 0; o < 8; o++) {
            float h = fmaxf(__ldg(agg2 + (size_t)n * 8 + o), 0.0f);
            s = fmaf(h, __ldg(Wlast + o), s);
        }
    }
    // segmented suffix-sum over sorted keys within a warp
#pragma unroll
    for (int d = 1; d < 32; d <<= 1) {
        float v = __shfl_down_sync(0xffffffffu, s, d);
        int gg   = __shfl_down_sync(0xffffffffu, g, d);
        if (lane + d < 32 && gg == g) s += v;
    }
    int gprev = __shfl_up_sync(0xffffffffu, g, 1);
    bool head = (lane == 0) || (gprev != g);
    if (valid && head) atomicAdd(out + g, s);
}

// -----------------------------------------------------------------------------
// Launch
// Inputs (metadata order): x, edge_index, edge_attr, batch,
//   We1, be1, root1, b1, We2, be2, root2, b2, Wlast, blast
// -----------------------------------------------------------------------------
extern "C" void kernel_launch(void* const* d_in, const int* in_sizes, int n_in,
                              void* d_out, int out_size)
{
    const float* x     = (const float*)d_in[0];
    const int*   ei    = (const int*)  d_in[1];
    const float* ea    = (const float*)d_in[2];
    const int*   batch = (const int*)  d_in[3];
    const float* We1   = (const float*)d_in[4];
    const float* be1   = (const float*)d_in[5];
    const float* root1 = (const float*)d_in[6];
    const float* b1    = (const float*)d_in[7];
    const float* We2   = (const float*)d_in[8];
    const float* be2   = (const float*)d_in[9];
    const float* root2 = (const float*)d_in[10];
    const float* b2    = (const float*)d_in[11];
    const float* Wlast = (const float*)d_in[12];
    const float* blast = (const float*)d_in[13];
    float* out = (float*)d_out;

    const int N = in_sizes[0] / 16;   // 50000
    const int E = in_sizes[1] / 2;    // 800000
    const int G = out_size;           // 512

    __half *pPm = nullptr, *pPb = nullptr;
    float *pA1 = nullptr, *pA2 = nullptr;
    cudaGetSymbolAddress((void**)&pPm, g_Pmain);
    cudaGetSymbolAddress((void**)&pPb, g_Pbias);
    cudaGetSymbolAddress((void**)&pA1, g_agg1);
    cudaGetSymbolAddress((void**)&pA2, g_agg2);

    const int TB = 256;
    const int nodeGrid = (N * 8 + TB - 1) / TB;
    const int nGroups = (E + 1) / 2;                 // 2 edges per group
    const int edgeGrid = (nGroups * 8 + TB - 1) / TB;

    // Layer 1
    node_prep_kernel<16, false><<<nodeGrid, TB>>>(x, We1, be1, root1, b1, pPm, pPb, pA1, N);
    edge_kernel<<<edgeGrid, TB>>>(ei, ea, pPm, pPb, pA1, E);
    // Layer 2 (relu of agg1 inside node_prep)
    node_prep_kernel<8, true><<<nodeGrid, TB>>>(pA1, We2, be2, root2, b2, pPm, pPb, pA2, N);
    edge_kernel<<<edgeGrid, TB>>>(ei, ea, pPm, pPb, pA2, E);
    // Pool + readout
    init_out_kernel<<<(G + TB - 1) / TB, TB>>>(out, blast, G);
    pool_kernel<<<(N + TB - 1) / TB, TB>>>(pA2, batch, Wlast, out, N);
}